// round 17
// baseline (speedup 1.0000x reference)
#include <cuda_runtime.h>
#include <cuda_bf16.h>
#include <cstdint>

#define NUM_CLASSES 100000
#define EMBED 512
#define BATCH_N 4096
#define LAMBDA_C 0.01f
#define ALPHA_C 0.1f

#define NCS ((size_t)NUM_CLASSES * EMBED)   // 51,200,000 floats
#define GRID (NUM_CLASSES / 8)               // 12,500 blocks, 8 rows each

// Zero-initialized at load; head blocks restore zeros each call, so the
// invariant holds across graph replays. g_head[c]: 0=untouched, i+1=head.
__device__ int g_head[NUM_CLASSES];
__device__ int g_next[BATCH_N];

// 1) build chains + zero loss slot
__global__ __launch_bounds__(256)
void build_kernel(const int* __restrict__ y, float* __restrict__ loss) {
    int i = blockIdx.x * blockDim.x + threadIdx.x;
    if (i == 0) *loss = 0.0f;
    if (i < BATCH_N) {
        int c = y[i];
        int old = atomicExch(&g_head[c], i + 1);
        g_next[i] = old;
    }
}

// Walk class chain, overwrite row r in dst, accumulate loss.
__device__ __forceinline__ void apply_row(int h, int r, int t,
                                          float4 c4,
                                          const float4* __restrict__ batch4,
                                          float* __restrict__ d,
                                          float* __restrict__ loss) {
    float ax = 0.f, ay = 0.f, az = 0.f, aw = 0.f, ls = 0.f;
    int s = h;
    while (s > 0) {
        float4 b4 = batch4[(size_t)(s - 1) * (EMBED / 4) + t];
        float dx = b4.x - c4.x;
        float dy = b4.y - c4.y;
        float dz = b4.z - c4.z;
        float dw = b4.w - c4.w;
        ax += dx; ay += dy; az += dz; aw += dw;
        ls += dx * dx + dy * dy + dz * dz + dw * dw;
        s = g_next[s - 1];
    }
    d[0] = c4.x + ALPHA_C * ax;
    d[1] = c4.y + ALPHA_C * ay;
    d[2] = c4.z + ALPHA_C * az;
    d[3] = c4.w + ALPHA_C * aw;

    #pragma unroll
    for (int off = 16; off > 0; off >>= 1)
        ls += __shfl_xor_sync(0xFFFFFFFFu, ls, off);
    if ((t & 31) == 0)
        atomicAdd(loss, ls * (LAMBDA_C / (float)BATCH_N));

    if (t == 0) g_head[r] = 0;              // restore zero-invariant
}

// 2) fused streaming pass, ILP=4: block handles 8 rows; each thread copies
//    one float4 from each of FOUR rows (independent loads). Head loads are
//    issued first; rare paths run after all copy stores.
__global__ __launch_bounds__(256)
void fused_copy_apply_kernel(const float4* __restrict__ centers4,
                             const float4* __restrict__ batch4,
                             float* __restrict__ dst,
                             float* __restrict__ loss) {
    const int bid = blockIdx.x;
    const int tid = threadIdx.x;
    const int t   = tid & 127;               // float4 index within a row
    const int r0  = bid * 8 + (tid >> 7);    // rows r0, r0+2, r0+4, r0+6

    // head loads first (resolved long before the branches)
    const int h0 = g_head[r0];
    const int h1 = g_head[r0 + 2];
    const int h2 = g_head[r0 + 4];
    const int h3 = g_head[r0 + 6];

    // four independent copy loads
    const size_t cb = (size_t)bid * 1024;    // block's first float4 chunk
    float4 A = __ldcs(centers4 + cb + tid);
    float4 B = __ldcs(centers4 + cb + 256 + tid);
    float4 C = __ldcs(centers4 + cb + 512 + tid);
    float4 D = __ldcs(centers4 + cb + 768 + tid);

    // copy stores (dst = out+1, misaligned -> scalars)
    float* d0 = dst + (size_t)r0 * EMBED + t * 4;
    float* d1 = d0 + 2 * EMBED;
    float* d2 = d0 + 4 * EMBED;
    float* d3 = d0 + 6 * EMBED;
    __stcs(d0 + 0, A.x); __stcs(d0 + 1, A.y); __stcs(d0 + 2, A.z); __stcs(d0 + 3, A.w);
    __stcs(d1 + 0, B.x); __stcs(d1 + 1, B.y); __stcs(d1 + 2, B.z); __stcs(d1 + 3, B.w);
    __stcs(d2 + 0, C.x); __stcs(d2 + 1, C.y); __stcs(d2 + 2, C.z); __stcs(d2 + 3, C.w);
    __stcs(d3 + 0, D.x); __stcs(d3 + 1, D.y); __stcs(d3 + 2, D.z); __stcs(d3 + 3, D.w);

    // rare overwrites (same-thread same-address: ordered after copy stores)
    if (h0 > 0) apply_row(h0, r0,     t, A, batch4, d0, loss);
    if (h1 > 0) apply_row(h1, r0 + 2, t, B, batch4, d1, loss);
    if (h2 > 0) apply_row(h2, r0 + 4, t, C, batch4, d2, loss);
    if (h3 > 0) apply_row(h3, r0 + 6, t, D, batch4, d3, loss);
}

extern "C" void kernel_launch(void* const* d_in, const int* in_sizes, int n_in,
                              void* d_out, int out_size) {
    const int*   y       = (const int*)d_in[0];
    const float* batch   = (const float*)d_in[1];
    const float* centers = (const float*)d_in[2];

    float* out = (float*)d_out;

    float* loss_ptr;
    float* new_centers;
    if (out_size == (int)(NCS + 1)) {
        loss_ptr = out;
        new_centers = out + 1;
    } else {
        new_centers = out;
        loss_ptr = out + NCS;
    }

    // 1) chains + loss zero
    build_kernel<<<(BATCH_N + 255) / 256, 256>>>(y, loss_ptr);

    // 2) fused streaming copy (ILP=4) + sparse overwrite
    fused_copy_apply_kernel<<<GRID, 256>>>(
        reinterpret_cast<const float4*>(centers),
        reinterpret_cast<const float4*>(batch),
        new_centers, loss_ptr);
}